// round 10
// baseline (speedup 1.0000x reference)
#include <cuda_runtime.h>
#include <cstdint>

// ============================ problem dims ============================
#define N_IMG 16
#define H_IMG 112
#define W_IMG 112
#define C_IN  256
#define C_OUT 256
#define H_PAD 114
#define W_PAD 114

// padded, packed int8 activations: [N][H_PAD][W_PAD][C_IN]  (~53 MB)
__device__ __align__(1024) uint8_t g_xp[(size_t)N_IMG * H_PAD * W_PAD * C_IN];
// packed int8 weights, tap-major: [9][C_OUT][C_IN]
__device__ __align__(1024) uint8_t g_w8[9 * C_OUT * C_IN];

// ============================ pack kernels ============================
__global__ void pack_x_kernel(const int* __restrict__ x) {
    int64_t i = (int64_t)blockIdx.x * blockDim.x + threadIdx.x;
    const int64_t total = (int64_t)N_IMG * H_PAD * W_PAD * 64;  // 4-byte words
    if (i >= total) return;
    int c4 = (int)(i & 63);
    int64_t p = i >> 6;
    int wp = (int)(p % W_PAD);
    int64_t t = p / W_PAD;
    int hp = (int)(t % H_PAD);
    int n  = (int)(t / H_PAD);
    uint32_t word = 0;
    if (hp >= 1 && hp <= H_IMG && wp >= 1 && wp <= W_IMG) {
        const int4 v = *reinterpret_cast<const int4*>(
            x + ((((int64_t)n * H_IMG + (hp - 1)) * W_IMG + (wp - 1)) * C_IN + c4 * 4));
        word = (v.x & 255) | ((v.y & 255) << 8) | ((v.z & 255) << 16) | ((v.w & 255) << 24);
    }
    reinterpret_cast<uint32_t*>(g_xp)[i] = word;
}

__global__ void pack_w_kernel(const int* __restrict__ w) {
    int i = blockIdx.x * blockDim.x + threadIdx.x;
    const int total = 9 * C_OUT * 64;
    if (i >= total) return;
    int c4 = i & 63;
    int t = i >> 6;
    int co = t % C_OUT;
    int tap = t / C_OUT;  // kh*3 + kw
    const int4 v = *reinterpret_cast<const int4*>(
        w + (((int64_t)co * 9 + tap) * C_IN + c4 * 4));
    uint32_t word = (v.x & 255) | ((v.y & 255) << 8) | ((v.z & 255) << 16) | ((v.w & 255) << 24);
    reinterpret_cast<uint32_t*>(g_w8)[i] = word;
}

// ============================ asm helpers ============================
#define CP_ASYNC_16(saddr, gaddr) \
    asm volatile("cp.async.cg.shared.global [%0], [%1], 16;" \
                 :: "r"(saddr), "l"(gaddr) : "memory")
#define CP_COMMIT() asm volatile("cp.async.commit_group;" ::: "memory")
#define CP_WAIT1()  asm volatile("cp.async.wait_group 1;" ::: "memory")

#define MMA_S8(d0, d1, d2, d3, a0, a1, a2, a3, b0, b1) \
    asm volatile("mma.sync.aligned.m16n8k32.row.col.s32.s8.s8.s32 " \
                 "{%0,%1,%2,%3}, {%4,%5,%6,%7}, {%8,%9}, {%0,%1,%2,%3};" \
                 : "+r"(d0), "+r"(d1), "+r"(d2), "+r"(d3) \
                 : "r"(a0), "r"(a1), "r"(a2), "r"(a3), "r"(b0), "r"(b1))

__device__ __forceinline__ uint32_t lds32(uint32_t addr) {
    uint32_t v;
    asm volatile("ld.shared.b32 %0, [%1];" : "=r"(v) : "r"(addr));
    return v;
}

// ============================ conv kernel ============================
// CTA: 128 consecutive output pixels x 128 couts (blockIdx.y selects half).
// 256 threads = 8 warps in a 2(M) x 4(N) grid; warp tile 64(M) x 32(N).
// K = 18 chunks of 128B (9 taps x 2 ci-halves).
// Stage: A 128 rows + B 128 rows, pitch 144B -> 36864B; 2 stages = 73728B
// => 2 CTAs/SM (register-limited), 16 warps/SM.
// Fragment feeds at PTX-ISA documented coordinates (proven in R8, rel_err=0).
// Output stored as FLOAT32 values (integer-exact).
static constexpr int PITCH       = 144;
static constexpr int BOFF        = 128 * PITCH;               // B region
static constexpr int STAGE_BYTES = (128 + 128) * PITCH;       // 36864
static constexpr int NUM_STAGES  = 2;
static constexpr int SMEM_DYN    = NUM_STAGES * STAGE_BYTES;  // 73728
static constexpr int NCHUNKS     = 18;

__global__ void __launch_bounds__(256, 2)
conv_kernel(float* __restrict__ out) {
    extern __shared__ uint8_t smem[];
    const uint32_t sbase = (uint32_t)__cvta_generic_to_shared(smem);

    const int tid  = threadIdx.x;
    const int lane = tid & 31;
    const int wid  = tid >> 5;
    const int warp_m = wid >> 2;       // 0..1  (64 M rows each)
    const int warp_n = wid & 3;        // 0..3  (32 couts each)
    const int g   = lane >> 2;         // group id 0..7
    const int tig = lane & 3;          // thread in group
    const int co_base = blockIdx.y * 128;

    // ---------------- cp.async addressing ----------------
    // A: row = tid & 127 (pixel), half = tid>>7 selects 64B half of 128B row.
    const int arow  = tid & 127;
    const int ahalf = tid >> 7;                 // 0 or 1
    const int m_pix = blockIdx.x * 128 + arow;
    const int n_img = m_pix / (H_IMG * W_IMG);
    const int rem   = m_pix % (H_IMG * W_IMG);
    const int h_out = rem / W_IMG;
    const int w_out = rem % W_IMG;
    const uint8_t* a_gbase = g_xp +
        (((int64_t)n_img * H_PAD + h_out) * W_PAD + w_out) * C_IN;
    const uint32_t a_sbase = (uint32_t)(arow * PITCH + ahalf * 64);

    // B: row = tid & 127 (cout within CTA), half = tid>>7.
    const int brow  = tid & 127;
    const uint8_t* b_gbase = g_w8 + (int64_t)(co_base + brow) * C_IN;
    const uint32_t b_sbase = (uint32_t)(BOFF + brow * PITCH + ahalf * 64);

    // ---------------- accumulators ----------------
    int d[4][4][4];
    #pragma unroll
    for (int mb = 0; mb < 4; mb++)
        #pragma unroll
        for (int nb = 0; nb < 4; nb++)
            #pragma unroll
            for (int q = 0; q < 4; q++) d[mb][nb][q] = 0;

    // ---------------- issue helper ----------------
    auto issue = [&](int s) {
        const int tap = s >> 1, ch = s & 1;
        const int kh = tap / 3, kw = tap % 3;
        const uint32_t stg = sbase + (s % NUM_STAGES) * STAGE_BYTES;
        const uint8_t* ga = a_gbase + ((int64_t)kh * W_PAD + kw) * C_IN
                          + ch * 128 + ahalf * 64;
        #pragma unroll
        for (int j = 0; j < 4; j++)
            CP_ASYNC_16(stg + a_sbase + j * 16, ga + j * 16);
        const uint8_t* gb = b_gbase + (int64_t)tap * (C_OUT * C_IN)
                          + ch * 128 + ahalf * 64;
        #pragma unroll
        for (int j = 0; j < 4; j++)
            CP_ASYNC_16(stg + b_sbase + j * 16, gb + j * 16);
    };

    issue(0); CP_COMMIT();
    issue(1); CP_COMMIT();

    // fragment base offsets (row part), col part added per ks
    uint32_t a_off[4];   // A[warp_m*64 + mb*16 + g][.]
    #pragma unroll
    for (int mb = 0; mb < 4; mb++)
        a_off[mb] = (uint32_t)((warp_m * 64 + mb * 16 + g) * PITCH + tig * 4);
    uint32_t b_off[4];   // Bt[warp_n*32 + nb*8 + g][.]
    #pragma unroll
    for (int nb = 0; nb < 4; nb++)
        b_off[nb] = (uint32_t)(BOFF + (warp_n * 32 + nb * 8 + g) * PITCH + tig * 4);

    // ---------------- main loop ----------------
    #pragma unroll 1
    for (int c = 0; c < NCHUNKS; c++) {
        CP_WAIT1();
        __syncthreads();
        const uint32_t stg = sbase + (c % NUM_STAGES) * STAGE_BYTES;

        #pragma unroll
        for (int ks = 0; ks < 4; ks++) {
            const uint32_t kcol = ks * 32;
            // A frags: a0=A[g][4t], a1=A[g+8][4t], a2=A[g][16+4t], a3=A[g+8][16+4t]
            uint32_t a[4][4];
            #pragma unroll
            for (int mb = 0; mb < 4; mb++) {
                const uint32_t p = stg + a_off[mb] + kcol;
                a[mb][0] = lds32(p);
                a[mb][1] = lds32(p + 8 * PITCH);
                a[mb][2] = lds32(p + 16);
                a[mb][3] = lds32(p + 8 * PITCH + 16);
            }
            // B frags: b0=Bt[g][4t], b1=Bt[g][16+4t]
            uint32_t b[4][2];
            #pragma unroll
            for (int nb = 0; nb < 4; nb++) {
                const uint32_t p = stg + b_off[nb] + kcol;
                b[nb][0] = lds32(p);
                b[nb][1] = lds32(p + 16);
            }
            #pragma unroll
            for (int mb = 0; mb < 4; mb++)
                #pragma unroll
                for (int nb = 0; nb < 4; nb++)
                    MMA_S8(d[mb][nb][0], d[mb][nb][1], d[mb][nb][2], d[mb][nb][3],
                           a[mb][0], a[mb][1], a[mb][2], a[mb][3],
                           b[nb][0], b[nb][1]);
        }

        __syncthreads();
        if (c + NUM_STAGES < NCHUNKS) { issue(c + NUM_STAGES); }
        CP_COMMIT();
    }

    // ---------------- epilogue: float32 values (integer-exact) ----------------
    // c0 -> D[g][2t], c1 -> D[g][2t+1], c2 -> D[g+8][2t], c3 -> D[g+8][2t+1]
    #pragma unroll
    for (int mb = 0; mb < 4; mb++) {
        const int m0 = blockIdx.x * 128 + warp_m * 64 + mb * 16 + g;
        #pragma unroll
        for (int nb = 0; nb < 4; nb++) {
            const int co = co_base + warp_n * 32 + nb * 8 + tig * 2;
            *reinterpret_cast<float2*>(out + (int64_t)m0 * C_OUT + co) =
                make_float2(__int2float_rn(d[mb][nb][0]), __int2float_rn(d[mb][nb][1]));
            *reinterpret_cast<float2*>(out + (int64_t)(m0 + 8) * C_OUT + co) =
                make_float2(__int2float_rn(d[mb][nb][2]), __int2float_rn(d[mb][nb][3]));
        }
    }
}

// ============================ host launch ============================
extern "C" void kernel_launch(void* const* d_in, const int* in_sizes, int n_in,
                              void* d_out, int out_size) {
    (void)out_size;
    // Bind inputs BY SIZE: x has 51,380,224 elements, weight has 589,824.
    const int* x = (const int*)d_in[0];
    const int* w = (const int*)d_in[1];
    if (n_in >= 2 && in_sizes[0] < in_sizes[1]) {
        x = (const int*)d_in[1];
        w = (const int*)d_in[0];
    }
    float* out = (float*)d_out;

    const int64_t totalx = (int64_t)N_IMG * H_PAD * W_PAD * 64;
    pack_x_kernel<<<(unsigned)((totalx + 255) / 256), 256>>>(x);
    pack_w_kernel<<<(9 * C_OUT * 64 + 255) / 256, 256>>>(w);

    cudaFuncSetAttribute(conv_kernel, cudaFuncAttributeMaxDynamicSharedMemorySize, SMEM_DYN);
    dim3 grid((N_IMG * H_IMG * W_IMG) / 128, 2);  // 1568 x 2
    conv_kernel<<<grid, 256, SMEM_DYN>>>(out);
}

// round 11
// speedup vs baseline: 1.4311x; 1.4311x over previous
#include <cuda_runtime.h>
#include <cuda_bf16.h>
#include <mma.h>
#include <cstdint>

using namespace nvcuda;

// ============================ problem dims ============================
#define N_IMG 16
#define H_IMG 112
#define W_IMG 112
#define C_IN  256
#define C_OUT 256
#define H_PAD 114
#define W_PAD 114

// padded activations as bf16: [N][H_PAD][W_PAD][C_IN]  (~106 MB)
__device__ __align__(1024) __nv_bfloat16 g_xbf[(size_t)N_IMG * H_PAD * W_PAD * C_IN];
// weights as bf16, tap-major: [9][C_OUT][C_IN]
__device__ __align__(1024) __nv_bfloat16 g_wbf[9 * C_OUT * C_IN];

// ============================ pack kernels ============================
__global__ void pack_x_kernel(const int* __restrict__ x) {
    int64_t i = (int64_t)blockIdx.x * blockDim.x + threadIdx.x;
    const int64_t total = (int64_t)N_IMG * H_PAD * W_PAD * 64;  // 4-channel units
    if (i >= total) return;
    int c4 = (int)(i & 63);
    int64_t p = i >> 6;
    int wp = (int)(p % W_PAD);
    int64_t t = p / W_PAD;
    int hp = (int)(t % H_PAD);
    int n  = (int)(t / H_PAD);
    uint2 wout = make_uint2(0u, 0u);
    if (hp >= 1 && hp <= H_IMG && wp >= 1 && wp <= W_IMG) {
        const int4 v = *reinterpret_cast<const int4*>(
            x + ((((int64_t)n * H_IMG + (hp - 1)) * W_IMG + (wp - 1)) * C_IN + c4 * 4));
        __nv_bfloat162 p0 = __floats2bfloat162_rn((float)v.x, (float)v.y);
        __nv_bfloat162 p1 = __floats2bfloat162_rn((float)v.z, (float)v.w);
        wout.x = *reinterpret_cast<uint32_t*>(&p0);
        wout.y = *reinterpret_cast<uint32_t*>(&p1);
    }
    reinterpret_cast<uint2*>(g_xbf)[i] = wout;
}

__global__ void pack_w_kernel(const int* __restrict__ w) {
    int i = blockIdx.x * blockDim.x + threadIdx.x;
    const int total = 9 * C_OUT * 64;
    if (i >= total) return;
    int c4 = i & 63;
    int t = i >> 6;
    int co = t % C_OUT;
    int tap = t / C_OUT;  // kh*3 + kw
    const int4 v = *reinterpret_cast<const int4*>(
        w + (((int64_t)co * 9 + tap) * C_IN + c4 * 4));
    __nv_bfloat162 p0 = __floats2bfloat162_rn((float)v.x, (float)v.y);
    __nv_bfloat162 p1 = __floats2bfloat162_rn((float)v.z, (float)v.w);
    reinterpret_cast<uint2*>(g_wbf)[i] = make_uint2(
        *reinterpret_cast<uint32_t*>(&p0), *reinterpret_cast<uint32_t*>(&p1));
}

// ============================ asm helpers ============================
#define CP_ASYNC_16(saddr, gaddr) \
    asm volatile("cp.async.cg.shared.global [%0], [%1], 16;" \
                 :: "r"(saddr), "l"(gaddr) : "memory")
#define CP_COMMIT() asm volatile("cp.async.commit_group;" ::: "memory")
#define CP_WAIT2()  asm volatile("cp.async.wait_group 2;" ::: "memory")

// ============================ conv kernel ============================
// CTA: 128 consecutive output pixels x all 256 couts. 512 threads = 16 warps,
// 4(M) x 4(N) warp grid, warp tile 32x64 = 2x4 wmma 16x16x16 bf16 tiles.
// K = 36 chunks of 64 bf16 channels (9 taps x 4 ci-quarters) = 128B/row.
// Stage: A 128 rows + B 256 rows, pitch 144B; 3 stages (166KB, 1 CTA/SM but
// 16 warps resident -- fixes R9's 8-warp starvation while keeping the clean
// pure-cp.async hot loop). wmma fragments + float32 epilogue (both proven).
static constexpr int PITCH_E     = 72;                         // bf16 elems
static constexpr int PITCH_B     = 144;                        // bytes
static constexpr int B_OFF_E     = 128 * PITCH_E;
static constexpr int B_OFF_B     = 128 * PITCH_B;
static constexpr int STAGE_E     = (128 + 256) * PITCH_E;
static constexpr int STAGE_B     = (128 + 256) * PITCH_B;      // 55296 bytes
static constexpr int NUM_STAGES  = 3;
static constexpr int SMEM_DYN    = NUM_STAGES * STAGE_B;       // 165888
static constexpr int NCHUNKS     = 36;

__global__ void __launch_bounds__(512, 1)
conv_kernel(float* __restrict__ out) {
    extern __shared__ __align__(128) __nv_bfloat16 sm[];
    const uint32_t sbase = (uint32_t)__cvta_generic_to_shared(sm);

    const int tid = threadIdx.x;
    const int wid = tid >> 5;
    const int wm  = wid >> 2;          // 0..3 (32 M rows each)
    const int wn  = wid & 3;           // 0..3 (64 couts each)
    const int m_base = blockIdx.x * 128;

    // ---------------- cp.async addressing ----------------
    // A: row = tid & 127 (pixel), quarter = tid>>7 selects 32B of the 128B row.
    const int arow = tid & 127;
    const int aq   = tid >> 7;         // 0..3
    const int m_pix = m_base + arow;
    const int n_img = m_pix / (H_IMG * W_IMG);
    const int rem   = m_pix % (H_IMG * W_IMG);
    const int h_out = rem / W_IMG;
    const int w_out = rem % W_IMG;
    const __nv_bfloat16* a_gbase = g_xbf +
        (((int64_t)n_img * H_PAD + h_out) * W_PAD + w_out) * C_IN;
    const uint32_t a_sbase = (uint32_t)(arow * PITCH_B + aq * 32);

    // B: row = tid & 255 (cout), half = tid>>8 selects 64B of the 128B row.
    const int brow  = tid & 255;
    const int bhalf = tid >> 8;        // 0 or 1
    const __nv_bfloat16* b_gbase = g_wbf + (int64_t)brow * C_IN;
    const uint32_t b_sbase = (uint32_t)(B_OFF_B + brow * PITCH_B + bhalf * 64);

    // ---------------- accumulators ----------------
    wmma::fragment<wmma::accumulator, 16, 16, 16, float> acc[2][4];
    #pragma unroll
    for (int mt = 0; mt < 2; mt++)
        #pragma unroll
        for (int nt = 0; nt < 4; nt++)
            wmma::fill_fragment(acc[mt][nt], 0.0f);

    // ---------------- issue helper ----------------
    // chunk s: tap = s>>2 (kh*3+kw), quarter = s&3 (64 channels = 128B)
    auto issue = [&](int s) {
        const int tap = s >> 2, ch = s & 3;
        const int kh = tap / 3, kw = tap % 3;
        const uint32_t stg = sbase + (s % NUM_STAGES) * STAGE_B;
        const uint8_t* ga = reinterpret_cast<const uint8_t*>(
            a_gbase + ((int64_t)kh * W_PAD + kw) * C_IN + ch * 64) + aq * 32;
        CP_ASYNC_16(stg + a_sbase,      ga);
        CP_ASYNC_16(stg + a_sbase + 16, ga + 16);
        const uint8_t* gb = reinterpret_cast<const uint8_t*>(
            b_gbase + (int64_t)tap * (C_OUT * C_IN) + ch * 64) + bhalf * 64;
        #pragma unroll
        for (int j = 0; j < 4; j++)
            CP_ASYNC_16(stg + b_sbase + j * 16, gb + j * 16);
    };

    issue(0); CP_COMMIT();
    issue(1); CP_COMMIT();
    issue(2); CP_COMMIT();

    // ---------------- main loop ----------------
    #pragma unroll 1
    for (int c = 0; c < NCHUNKS; c++) {
        CP_WAIT2();
        __syncthreads();
        const __nv_bfloat16* stg = sm + (c % NUM_STAGES) * STAGE_E;

        #pragma unroll
        for (int ks = 0; ks < 4; ks++) {
            wmma::fragment<wmma::matrix_a, 16, 16, 16, __nv_bfloat16,
                           wmma::row_major> af[2];
            #pragma unroll
            for (int mt = 0; mt < 2; mt++)
                wmma::load_matrix_sync(
                    af[mt], stg + (wm * 32 + mt * 16) * PITCH_E + ks * 16, PITCH_E);
            #pragma unroll
            for (int nt = 0; nt < 4; nt++) {
                wmma::fragment<wmma::matrix_b, 16, 16, 16, __nv_bfloat16,
                               wmma::col_major> bf;
                wmma::load_matrix_sync(
                    bf, stg + B_OFF_E + (wn * 64 + nt * 16) * PITCH_E + ks * 16,
                    PITCH_E);
                #pragma unroll
                for (int mt = 0; mt < 2; mt++)
                    wmma::mma_sync(acc[mt][nt], af[mt], bf, acc[mt][nt]);
            }
        }

        __syncthreads();
        if (c + NUM_STAGES < NCHUNKS) issue(c + NUM_STAGES);
        CP_COMMIT();
    }

    // ---------------- epilogue: float32 values (integer-exact) ----------------
    #pragma unroll
    for (int mt = 0; mt < 2; mt++)
        #pragma unroll
        for (int nt = 0; nt < 4; nt++) {
            float* dst = out
                       + (int64_t)(m_base + wm * 32 + mt * 16) * C_OUT
                       + wn * 64 + nt * 16;
            wmma::store_matrix_sync(dst, acc[mt][nt], C_OUT, wmma::mem_row_major);
        }
}

// ============================ host launch ============================
extern "C" void kernel_launch(void* const* d_in, const int* in_sizes, int n_in,
                              void* d_out, int out_size) {
    (void)out_size;
    // Bind inputs BY SIZE: x has 51,380,224 elements, weight has 589,824.
    const int* x = (const int*)d_in[0];
    const int* w = (const int*)d_in[1];
    if (n_in >= 2 && in_sizes[0] < in_sizes[1]) {
        x = (const int*)d_in[1];
        w = (const int*)d_in[0];
    }
    float* out = (float*)d_out;

    const int64_t totalx = (int64_t)N_IMG * H_PAD * W_PAD * 64;
    pack_x_kernel<<<(unsigned)((totalx + 255) / 256), 256>>>(x);
    pack_w_kernel<<<(9 * C_OUT * 64 + 255) / 256, 256>>>(w);

    cudaFuncSetAttribute(conv_kernel, cudaFuncAttributeMaxDynamicSharedMemorySize, SMEM_DYN);
    const int grid = (N_IMG * H_IMG * W_IMG) / 128;  // 1568
    conv_kernel<<<grid, 512, SMEM_DYN>>>(out);
}

// round 12
// speedup vs baseline: 1.5470x; 1.0810x over previous
#include <cuda_runtime.h>
#include <cuda_fp16.h>
#include <mma.h>
#include <cstdint>

using namespace nvcuda;

// ============================ problem dims ============================
#define N_IMG 16
#define H_IMG 112
#define W_IMG 112
#define C_IN  256
#define C_OUT 256
#define H_PAD 114
#define W_PAD 114

// padded activations as fp16: [N][H_PAD][W_PAD][C_IN]  (~106 MB)
__device__ __align__(1024) __half g_xh[(size_t)N_IMG * H_PAD * W_PAD * C_IN];
// weights as fp16, tap-major: [9][C_OUT][C_IN]
__device__ __align__(1024) __half g_wh[9 * C_OUT * C_IN];

// ============================ fused pack kernel ============================
// First XUNITS threads handle activations (4 channels per unit, zero-padded
// borders); the next WUNITS handle weights (tap-major transpose).
static constexpr int64_t XUNITS = (int64_t)N_IMG * H_PAD * W_PAD * 64;
static constexpr int     WUNITS = 9 * C_OUT * 64;

__global__ void pack_kernel(const int* __restrict__ x, const int* __restrict__ w) {
    int64_t i = (int64_t)blockIdx.x * blockDim.x + threadIdx.x;
    if (i < XUNITS) {
        int c4 = (int)(i & 63);
        int64_t p = i >> 6;
        int wp = (int)(p % W_PAD);
        int64_t t = p / W_PAD;
        int hp = (int)(t % H_PAD);
        int n  = (int)(t / H_PAD);
        uint2 wout = make_uint2(0u, 0u);
        if (hp >= 1 && hp <= H_IMG && wp >= 1 && wp <= W_IMG) {
            const int4 v = *reinterpret_cast<const int4*>(
                x + ((((int64_t)n * H_IMG + (hp - 1)) * W_IMG + (wp - 1)) * C_IN + c4 * 4));
            __half2 p0 = __floats2half2_rn((float)v.x, (float)v.y);
            __half2 p1 = __floats2half2_rn((float)v.z, (float)v.w);
            wout.x = *reinterpret_cast<uint32_t*>(&p0);
            wout.y = *reinterpret_cast<uint32_t*>(&p1);
        }
        reinterpret_cast<uint2*>(g_xh)[i] = wout;
    } else {
        int64_t j = i - XUNITS;
        if (j >= WUNITS) return;
        int c4 = (int)(j & 63);
        int t = (int)(j >> 6);
        int co = t % C_OUT;
        int tap = t / C_OUT;  // kh*3 + kw
        const int4 v = *reinterpret_cast<const int4*>(
            w + (((int64_t)co * 9 + tap) * C_IN + c4 * 4));
        __half2 p0 = __floats2half2_rn((float)v.x, (float)v.y);
        __half2 p1 = __floats2half2_rn((float)v.z, (float)v.w);
        reinterpret_cast<uint2*>(g_wh)[j] = make_uint2(
            *reinterpret_cast<uint32_t*>(&p0), *reinterpret_cast<uint32_t*>(&p1));
    }
}

// ============================ asm helpers ============================
#define CP_ASYNC_16(saddr, gaddr) \
    asm volatile("cp.async.cg.shared.global [%0], [%1], 16;" \
                 :: "r"(saddr), "l"(gaddr) : "memory")
#define CP_COMMIT() asm volatile("cp.async.commit_group;" ::: "memory")
#define CP_WAIT2()  asm volatile("cp.async.wait_group 2;" ::: "memory")

// ============================ conv kernel ============================
// CTA: 128 consecutive output pixels x all 256 couts. 512 threads = 16 warps,
// 4(M) x 4(N) warp grid, warp tile 32x64 = 2x4 wmma 16x16x16 fp16 tiles.
// K = 36 chunks of 64 fp16 channels (9 taps x 4 ci-quarters) = 128B/row.
// Stage: A 128 rows + B 256 rows, pitch 144B; 3 stages. Pure cp.async hot
// loop; wmma fragments; f32 accum; float32-value epilogue (all proven).
static constexpr int PITCH_E     = 72;                         // fp16 elems
static constexpr int PITCH_B     = 144;                        // bytes
static constexpr int B_OFF_E     = 128 * PITCH_E;
static constexpr int B_OFF_B     = 128 * PITCH_B;
static constexpr int STAGE_E     = (128 + 256) * PITCH_E;
static constexpr int STAGE_B     = (128 + 256) * PITCH_B;      // 55296 bytes
static constexpr int NUM_STAGES  = 3;
static constexpr int SMEM_DYN    = NUM_STAGES * STAGE_B;       // 165888
static constexpr int NCHUNKS     = 36;

__global__ void __launch_bounds__(512, 1)
conv_kernel(float* __restrict__ out) {
    extern __shared__ __align__(128) __half sm[];
    const uint32_t sbase = (uint32_t)__cvta_generic_to_shared(sm);

    const int tid = threadIdx.x;
    const int wid = tid >> 5;
    const int wm  = wid >> 2;          // 0..3 (32 M rows each)
    const int wn  = wid & 3;           // 0..3 (64 couts each)
    const int m_base = blockIdx.x * 128;

    // ---------------- cp.async addressing ----------------
    const int arow = tid & 127;
    const int aq   = tid >> 7;         // 0..3, selects 32B of the 128B row
    const int m_pix = m_base + arow;
    const int n_img = m_pix / (H_IMG * W_IMG);
    const int rem   = m_pix % (H_IMG * W_IMG);
    const int h_out = rem / W_IMG;
    const int w_out = rem % W_IMG;
    const __half* a_gbase = g_xh +
        (((int64_t)n_img * H_PAD + h_out) * W_PAD + w_out) * C_IN;
    const uint32_t a_sbase = (uint32_t)(arow * PITCH_B + aq * 32);

    const int brow  = tid & 255;
    const int bhalf = tid >> 8;        // 0 or 1, selects 64B of the 128B row
    const __half* b_gbase = g_wh + (int64_t)brow * C_IN;
    const uint32_t b_sbase = (uint32_t)(B_OFF_B + brow * PITCH_B + bhalf * 64);

    // ---------------- accumulators ----------------
    wmma::fragment<wmma::accumulator, 16, 16, 16, float> acc[2][4];
    #pragma unroll
    for (int mt = 0; mt < 2; mt++)
        #pragma unroll
        for (int nt = 0; nt < 4; nt++)
            wmma::fill_fragment(acc[mt][nt], 0.0f);

    // ---------------- issue helper ----------------
    auto issue = [&](int s) {
        const int tap = s >> 2, ch = s & 3;
        const int kh = tap / 3, kw = tap % 3;
        const uint32_t stg = sbase + (s % NUM_STAGES) * STAGE_B;
        const uint8_t* ga = reinterpret_cast<const uint8_t*>(
            a_gbase + ((int64_t)kh * W_PAD + kw) * C_IN + ch * 64) + aq * 32;
        CP_ASYNC_16(stg + a_sbase,      ga);
        CP_ASYNC_16(stg + a_sbase + 16, ga + 16);
        const uint8_t* gb = reinterpret_cast<const uint8_t*>(
            b_gbase + (int64_t)tap * (C_OUT * C_IN) + ch * 64) + bhalf * 64;
        #pragma unroll
        for (int j = 0; j < 4; j++)
            CP_ASYNC_16(stg + b_sbase + j * 16, gb + j * 16);
    };

    issue(0); CP_COMMIT();
    issue(1); CP_COMMIT();
    issue(2); CP_COMMIT();

    // ---------------- main loop ----------------
    #pragma unroll 1
    for (int c = 0; c < NCHUNKS; c++) {
        CP_WAIT2();
        __syncthreads();
        const __half* stg = sm + (c % NUM_STAGES) * STAGE_E;

        #pragma unroll
        for (int ks = 0; ks < 4; ks++) {
            wmma::fragment<wmma::matrix_a, 16, 16, 16, __half,
                           wmma::row_major> af[2];
            #pragma unroll
            for (int mt = 0; mt < 2; mt++)
                wmma::load_matrix_sync(
                    af[mt], stg + (wm * 32 + mt * 16) * PITCH_E + ks * 16, PITCH_E);
            #pragma unroll
            for (int nt = 0; nt < 4; nt++) {
                wmma::fragment<wmma::matrix_b, 16, 16, 16, __half,
                               wmma::col_major> bf;
                wmma::load_matrix_sync(
                    bf, stg + B_OFF_E + (wn * 64 + nt * 16) * PITCH_E + ks * 16,
                    PITCH_E);
                #pragma unroll
                for (int mt = 0; mt < 2; mt++)
                    wmma::mma_sync(acc[mt][nt], af[mt], bf, acc[mt][nt]);
            }
        }

        __syncthreads();
        if (c + NUM_STAGES < NCHUNKS) issue(c + NUM_STAGES);
        CP_COMMIT();
    }

    // ---------------- epilogue: float32 values (integer-exact) ----------------
    #pragma unroll
    for (int mt = 0; mt < 2; mt++)
        #pragma unroll
        for (int nt = 0; nt < 4; nt++) {
            float* dst = out
                       + (int64_t)(m_base + wm * 32 + mt * 16) * C_OUT
                       + wn * 64 + nt * 16;
            wmma::store_matrix_sync(dst, acc[mt][nt], C_OUT, wmma::mem_row_major);
        }
}

// ============================ host launch ============================
extern "C" void kernel_launch(void* const* d_in, const int* in_sizes, int n_in,
                              void* d_out, int out_size) {
    (void)out_size;
    // Bind inputs BY SIZE: x has 51,380,224 elements, weight has 589,824.
    const int* x = (const int*)d_in[0];
    const int* w = (const int*)d_in[1];
    if (n_in >= 2 && in_sizes[0] < in_sizes[1]) {
        x = (const int*)d_in[1];
        w = (const int*)d_in[0];
    }
    float* out = (float*)d_out;

    const int64_t total_units = XUNITS + WUNITS;
    pack_kernel<<<(unsigned)((total_units + 255) / 256), 256>>>(x, w);

    cudaFuncSetAttribute(conv_kernel, cudaFuncAttributeMaxDynamicSharedMemorySize, SMEM_DYN);
    const int grid = (N_IMG * H_IMG * W_IMG) / 128;  // 1568
    conv_kernel<<<grid, 512, SMEM_DYN>>>(out);
}

// round 13
// speedup vs baseline: 2.7309x; 1.7653x over previous
#include <cuda_runtime.h>
#include <cuda_fp16.h>
#include <cuda.h>
#include <cstdint>

// ============================ problem dims ============================
#define N_IMG 16
#define H_IMG 112
#define W_IMG 112
#define C_IN  256
#define C_OUT 256
#define H_PAD 114
#define W_PAD 114
static constexpr int TOTAL_POS = N_IMG * H_PAD * W_PAD;   // 207936 padded positions

// padded activations as fp16: [pos][C_IN]  (~106 MB)
__device__ __align__(1024) __half g_xh[(size_t)TOTAL_POS * C_IN];
// weights as fp16, tap-major: [9][C_OUT][C_IN]
__device__ __align__(1024) __half g_wh[9 * C_OUT * C_IN];

// ============================ fused pack kernel (proven R12) ============================
static constexpr int64_t XUNITS = (int64_t)TOTAL_POS * 64;
static constexpr int     WUNITS = 9 * C_OUT * 64;

__global__ void pack_kernel(const int* __restrict__ x, const int* __restrict__ w) {
    int64_t i = (int64_t)blockIdx.x * blockDim.x + threadIdx.x;
    if (i < XUNITS) {
        int c4 = (int)(i & 63);
        int64_t p = i >> 6;
        int wp = (int)(p % W_PAD);
        int64_t t = p / W_PAD;
        int hp = (int)(t % H_PAD);
        int n  = (int)(t / H_PAD);
        uint2 wout = make_uint2(0u, 0u);
        if (hp >= 1 && hp <= H_IMG && wp >= 1 && wp <= W_IMG) {
            const int4 v = *reinterpret_cast<const int4*>(
                x + ((((int64_t)n * H_IMG + (hp - 1)) * W_IMG + (wp - 1)) * C_IN + c4 * 4));
            __half2 p0 = __floats2half2_rn((float)v.x, (float)v.y);
            __half2 p1 = __floats2half2_rn((float)v.z, (float)v.w);
            wout.x = *reinterpret_cast<uint32_t*>(&p0);
            wout.y = *reinterpret_cast<uint32_t*>(&p1);
        }
        reinterpret_cast<uint2*>(g_xh)[i] = wout;
    } else {
        int64_t j = i - XUNITS;
        if (j >= WUNITS) return;
        int c4 = (int)(j & 63);
        int t = (int)(j >> 6);
        int co = t % C_OUT;
        int tap = t / C_OUT;
        const int4 v = *reinterpret_cast<const int4*>(
            w + (((int64_t)co * 9 + tap) * C_IN + c4 * 4));
        __half2 p0 = __floats2half2_rn((float)v.x, (float)v.y);
        __half2 p1 = __floats2half2_rn((float)v.z, (float)v.w);
        reinterpret_cast<uint2*>(g_wh)[j] = make_uint2(
            *reinterpret_cast<uint32_t*>(&p0), *reinterpret_cast<uint32_t*>(&p1));
    }
}

// ============================ PTX helpers ============================
#define MBAR_INIT(addr, cnt) \
    asm volatile("mbarrier.init.shared.b64 [%0], %1;" :: "r"(addr), "r"(cnt) : "memory")
#define MBAR_EXPECT_TX(addr, bytes) \
    asm volatile("mbarrier.arrive.expect_tx.shared.b64 _, [%0], %1;" \
                 :: "r"(addr), "r"(bytes) : "memory")
#define MBAR_WAIT(addr, ph) do {                                             \
    uint32_t _m = (addr); uint32_t _p = (ph); uint32_t _d;                   \
    asm volatile("{\n\t.reg .pred p;\n\t"                                    \
        "mbarrier.try_wait.parity.acquire.cta.shared::cta.b64 p, [%1], %2;\n\t" \
        "selp.b32 %0, 1, 0, p;\n\t}"                                         \
        : "=r"(_d) : "r"(_m), "r"(_p) : "memory");                           \
    if (!_d) {                                                               \
        asm volatile("{\n\t.reg .pred P1;\n\t"                               \
            "WL_%=:\n\t"                                                     \
            "mbarrier.try_wait.parity.acquire.cta.shared::cta.b64 P1, [%0], %1, 0x989680;\n\t" \
            "@P1 bra.uni WD_%=;\n\t"                                         \
            "bra.uni WL_%=;\n\t"                                             \
            "WD_%=:\n\t}"                                                    \
            :: "r"(_m), "r"(_p) : "memory");                                 \
    } } while (0)
#define TMA2D(dst, map, cx, cy, mbar) \
    asm volatile("cp.async.bulk.tensor.2d.shared::cta.global.tile.mbarrier::complete_tx::bytes " \
                 "[%0], [%1, {%2, %3}], [%4];"                               \
                 :: "r"(dst), "l"(map), "r"(cx), "r"(cy), "r"(mbar) : "memory")

#define MMA_F16(d0, d1, d2, d3, a0, a1, a2, a3, b0, b1) \
    asm volatile("mma.sync.aligned.m16n8k16.row.col.f32.f16.f16.f32 " \
                 "{%0,%1,%2,%3}, {%4,%5,%6,%7}, {%8,%9}, {%0,%1,%2,%3};" \
                 : "+f"(d0), "+f"(d1), "+f"(d2), "+f"(d3) \
                 : "r"(a0), "r"(a1), "r"(a2), "r"(a3), "r"(b0), "r"(b1))

__device__ __forceinline__ uint32_t lds32(uint32_t addr) {
    uint32_t v;
    asm volatile("ld.shared.b32 %0, [%1];" : "=r"(v) : "r"(addr));
    return v;
}

// ============================ conv kernel ============================
// CTA: 128 consecutive PADDED positions x 256 couts. Any tap (kh,kw) is then a
// contiguous 128-row box at offset (kh-1)*114+(kw-1): one 2D TMA per tap-chunk.
// Invalid positions (border padding) are masked at store (~3.6% waste).
// 512 threads = 16 warps, 4(M) x 4(N), warp tile 32x64, fp16 m16n8k16 MMA.
// 36 chunks (9 taps x 4 ch-quarters). Stage = A 16KB + B 32KB (SW128), 3 stages.
// Fragment LDS at R8-proven byte coordinates (identical bytes for f16 k16 and
// s8 k32), with the TMA SW128 XOR folded in. Output = float32 values (proven).
static constexpr int A_BYTES   = 128 * 128;                 // 16384
static constexpr int B_BYTES   = 256 * 128;                 // 32768
static constexpr int STAGE_B   = A_BYTES + B_BYTES;         // 49152
static constexpr int NSTAGES   = 3;
static constexpr int TILES_B   = NSTAGES * STAGE_B;         // 147456
static constexpr int SMEM_DYN  = 1024 + TILES_B + 64;
static constexpr int NCHUNKS   = 36;
static constexpr int NCTA      = (TOTAL_POS + 127) / 128;   // 1625

__global__ void __launch_bounds__(512, 1)
conv_kernel(const __grid_constant__ CUtensorMap mapA,
            const __grid_constant__ CUtensorMap mapB,
            float* __restrict__ out) {
    extern __shared__ uint8_t smraw[];
    const uint32_t sb = ((uint32_t)__cvta_generic_to_shared(smraw) + 1023u) & ~1023u;
    const uint32_t bar0 = sb + TILES_B;

    const int tid  = threadIdx.x;
    const int lane = tid & 31;
    const int wid  = tid >> 5;
    const int warp_m = wid >> 2;       // 0..3 (32 M rows each)
    const int wn     = wid & 3;        // 0..3 (64 couts each)
    const int g   = lane >> 2;
    const int tig = lane & 3;
    const int p0  = blockIdx.x * 128;  // first padded position of this CTA

    if (tid == 0) {
        #pragma unroll
        for (int i = 0; i < NSTAGES; i++) MBAR_INIT(bar0 + i * 8, 1);
    }
    __syncthreads();

    // ---------------- TMA issue helper (single thread) ----------------
    auto issue = [&](int s) {
        const int slot = s % NSTAGES;
        const int tap = s >> 2, ch = s & 3;
        const int kh = tap / 3, kw = tap % 3;
        const uint32_t stg = sb + slot * STAGE_B;
        const uint32_t bar = bar0 + slot * 8;
        MBAR_EXPECT_TX(bar, (uint32_t)STAGE_B);
        TMA2D(stg,           &mapA, ch * 64, p0 + (kh - 1) * W_PAD + (kw - 1), bar);
        TMA2D(stg + A_BYTES, &mapB, ch * 64, tap * 256, bar);
    };

    if (tid == 0) { issue(0); issue(1); issue(2); }

    // ---------------- fragment addressing (R8-proven coordinates) ----------------
    const uint32_t xr = (uint32_t)g << 4;     // SW128 XOR mask (all rows = g mod 8)
    uint32_t offA[2];
    #pragma unroll
    for (int mb = 0; mb < 2; mb++)
        offA[mb] = (uint32_t)((warp_m * 32 + mb * 16 + g) * 128);
    uint32_t offB[8];
    #pragma unroll
    for (int nb = 0; nb < 8; nb++)
        offB[nb] = (uint32_t)(A_BYTES + (wn * 64 + nb * 8 + g) * 128);

    float d[2][8][4];
    #pragma unroll
    for (int mb = 0; mb < 2; mb++)
        #pragma unroll
        for (int nb = 0; nb < 8; nb++)
            #pragma unroll
            for (int q = 0; q < 4; q++) d[mb][nb][q] = 0.0f;

    // ---------------- main loop ----------------
    #pragma unroll 1
    for (int c = 0; c < NCHUNKS; c++) {
        const int slot = c % NSTAGES;
        MBAR_WAIT(bar0 + slot * 8, (c / NSTAGES) & 1);
        const uint32_t stg = sb + slot * STAGE_B;

        #pragma unroll
        for (int ks = 0; ks < 4; ks++) {
            const uint32_t c0 = ((uint32_t)(ks * 32 + tig * 4)) ^ xr;
            const uint32_t c1 = ((uint32_t)(ks * 32 + 16 + tig * 4)) ^ xr;
            uint32_t a[2][4];
            #pragma unroll
            for (int mb = 0; mb < 2; mb++) {
                const uint32_t p = stg + offA[mb];
                a[mb][0] = lds32(p + c0);
                a[mb][1] = lds32(p + 1024 + c0);   // +8 rows
                a[mb][2] = lds32(p + c1);
                a[mb][3] = lds32(p + 1024 + c1);
            }
            uint32_t b[8][2];
            #pragma unroll
            for (int nb = 0; nb < 8; nb++) {
                const uint32_t p = stg + offB[nb];
                b[nb][0] = lds32(p + c0);
                b[nb][1] = lds32(p + c1);
            }
            #pragma unroll
            for (int mb = 0; mb < 2; mb++)
                #pragma unroll
                for (int nb = 0; nb < 8; nb++)
                    MMA_F16(d[mb][nb][0], d[mb][nb][1], d[mb][nb][2], d[mb][nb][3],
                            a[mb][0], a[mb][1], a[mb][2], a[mb][3],
                            b[nb][0], b[nb][1]);
        }

        __syncthreads();                     // all warps done with this slot
        if (tid == 0 && c + NSTAGES < NCHUNKS) issue(c + NSTAGES);
    }

    // ---------------- epilogue: mask invalid padded positions, store f32 ----------------
    #pragma unroll
    for (int mb = 0; mb < 2; mb++) {
        #pragma unroll
        for (int r = 0; r < 2; r++) {        // row g and g+8
            const int pos = p0 + warp_m * 32 + mb * 16 + g + r * 8;
            if (pos >= TOTAL_POS) continue;
            const int n  = pos / (H_PAD * W_PAD);
            const int rm = pos % (H_PAD * W_PAD);
            const int hp = rm / W_PAD;
            const int wp = rm % W_PAD;
            if (hp < 1 || hp > H_IMG || wp < 1 || wp > W_IMG) continue;
            const int64_t obase =
                (((int64_t)n * H_IMG + (hp - 1)) * W_IMG + (wp - 1)) * C_OUT;
            #pragma unroll
            for (int nb = 0; nb < 8; nb++) {
                const int co = wn * 64 + nb * 8 + tig * 2;
                *reinterpret_cast<float2*>(out + obase + co) =
                    make_float2(d[mb][nb][2 * r], d[mb][nb][2 * r + 1]);
            }
        }
    }
}

// ============================ host launch ============================
typedef CUresult (*TmapEncodeFn)(
    CUtensorMap*, CUtensorMapDataType, cuuint32_t, void*,
    const cuuint64_t*, const cuuint64_t*, const cuuint32_t*, const cuuint32_t*,
    CUtensorMapInterleave, CUtensorMapSwizzle, CUtensorMapL2promotion,
    CUtensorMapFloatOOBfill);

extern "C" void kernel_launch(void* const* d_in, const int* in_sizes, int n_in,
                              void* d_out, int out_size) {
    (void)out_size;
    // Bind inputs BY SIZE: x has 51,380,224 elements, weight has 589,824.
    const int* x = (const int*)d_in[0];
    const int* w = (const int*)d_in[1];
    if (n_in >= 2 && in_sizes[0] < in_sizes[1]) {
        x = (const int*)d_in[1];
        w = (const int*)d_in[0];
    }
    float* out = (float*)d_out;

    const int64_t total_units = XUNITS + WUNITS;
    pack_kernel<<<(unsigned)((total_units + 255) / 256), 256>>>(x, w);

    // tensormaps
    void* xp = nullptr; void* wp = nullptr;
    cudaGetSymbolAddress(&xp, g_xh);
    cudaGetSymbolAddress(&wp, g_wh);

    TmapEncodeFn enc = nullptr;
    cudaDriverEntryPointQueryResult qres;
    cudaGetDriverEntryPointByVersion("cuTensorMapEncodeTiled", (void**)&enc,
                                     12000, cudaEnableDefault, &qres);

    CUtensorMap mapA, mapB;
    {
        cuuint64_t dims[2]    = {C_IN, (cuuint64_t)TOTAL_POS};
        cuuint64_t strides[1] = {C_IN * 2};                   // bytes
        cuuint32_t box[2]     = {64, 128};
        cuuint32_t es[2]      = {1, 1};
        enc(&mapA, CU_TENSOR_MAP_DATA_TYPE_FLOAT16, 2, xp, dims, strides, box, es,
            CU_TENSOR_MAP_INTERLEAVE_NONE, CU_TENSOR_MAP_SWIZZLE_128B,
            CU_TENSOR_MAP_L2_PROMOTION_L2_128B, CU_TENSOR_MAP_FLOAT_OOB_FILL_NONE);
    }
    {
        cuuint64_t dims[2]    = {C_IN, 9 * C_OUT};
        cuuint64_t strides[1] = {C_IN * 2};
        cuuint32_t box[2]     = {64, 256};
        cuuint32_t es[2]      = {1, 1};
        enc(&mapB, CU_TENSOR_MAP_DATA_TYPE_FLOAT16, 2, wp, dims, strides, box, es,
            CU_TENSOR_MAP_INTERLEAVE_NONE, CU_TENSOR_MAP_SWIZZLE_128B,
            CU_TENSOR_MAP_L2_PROMOTION_L2_128B, CU_TENSOR_MAP_FLOAT_OOB_FILL_NONE);
    }

    cudaFuncSetAttribute(conv_kernel, cudaFuncAttributeMaxDynamicSharedMemorySize, SMEM_DYN);
    conv_kernel<<<NCTA, 512, SMEM_DYN>>>(mapA, mapB, out);
}

// round 14
// speedup vs baseline: 2.9097x; 1.0655x over previous
#include <cuda_runtime.h>
#include <cuda_fp16.h>
#include <cuda.h>
#include <cstdint>

// ============================ problem dims ============================
#define N_IMG 16
#define H_IMG 112
#define W_IMG 112
#define C_IN  256
#define C_OUT 256
#define H_PAD 114
#define W_PAD 114
static constexpr int TOTAL_POS = N_IMG * H_PAD * W_PAD;   // 207936 padded positions

// padded activations as fp16: [pos][C_IN]  (~106 MB)
__device__ __align__(1024) __half g_xh[(size_t)TOTAL_POS * C_IN];
// weights as fp16, tap-major: [9][C_OUT][C_IN]
__device__ __align__(1024) __half g_wh[9 * C_OUT * C_IN];

// ============================ fused pack kernel (proven) ============================
static constexpr int64_t XUNITS = (int64_t)TOTAL_POS * 64;
static constexpr int     WUNITS = 9 * C_OUT * 64;

__global__ void pack_kernel(const int* __restrict__ x, const int* __restrict__ w) {
    int64_t i = (int64_t)blockIdx.x * blockDim.x + threadIdx.x;
    if (i < XUNITS) {
        int c4 = (int)(i & 63);
        int64_t p = i >> 6;
        int wp = (int)(p % W_PAD);
        int64_t t = p / W_PAD;
        int hp = (int)(t % H_PAD);
        int n  = (int)(t / H_PAD);
        uint2 wout = make_uint2(0u, 0u);
        if (hp >= 1 && hp <= H_IMG && wp >= 1 && wp <= W_IMG) {
            const int4 v = *reinterpret_cast<const int4*>(
                x + ((((int64_t)n * H_IMG + (hp - 1)) * W_IMG + (wp - 1)) * C_IN + c4 * 4));
            __half2 p0 = __floats2half2_rn((float)v.x, (float)v.y);
            __half2 p1 = __floats2half2_rn((float)v.z, (float)v.w);
            wout.x = *reinterpret_cast<uint32_t*>(&p0);
            wout.y = *reinterpret_cast<uint32_t*>(&p1);
        }
        reinterpret_cast<uint2*>(g_xh)[i] = wout;
    } else {
        int64_t j = i - XUNITS;
        if (j >= WUNITS) return;
        int c4 = (int)(j & 63);
        int t = (int)(j >> 6);
        int co = t % C_OUT;
        int tap = t / C_OUT;
        const int4 v = *reinterpret_cast<const int4*>(
            w + (((int64_t)co * 9 + tap) * C_IN + c4 * 4));
        __half2 p0 = __floats2half2_rn((float)v.x, (float)v.y);
        __half2 p1 = __floats2half2_rn((float)v.z, (float)v.w);
        reinterpret_cast<uint2*>(g_wh)[j] = make_uint2(
            *reinterpret_cast<uint32_t*>(&p0), *reinterpret_cast<uint32_t*>(&p1));
    }
}

// ============================ PTX helpers ============================
#define MBAR_INIT(addr, cnt) \
    asm volatile("mbarrier.init.shared.b64 [%0], %1;" :: "r"(addr), "r"(cnt) : "memory")
#define MBAR_EXPECT_TX(addr, bytes) \
    asm volatile("mbarrier.arrive.expect_tx.shared.b64 _, [%0], %1;" \
                 :: "r"(addr), "r"(bytes) : "memory")
#define MBAR_WAIT(addr, ph) do {                                             \
    uint32_t _m = (addr); uint32_t _p = (ph); uint32_t _d;                   \
    asm volatile("{\n\t.reg .pred p;\n\t"                                    \
        "mbarrier.try_wait.parity.acquire.cta.shared::cta.b64 p, [%1], %2;\n\t" \
        "selp.b32 %0, 1, 0, p;\n\t}"                                         \
        : "=r"(_d) : "r"(_m), "r"(_p) : "memory");                           \
    if (!_d) {                                                               \
        asm volatile("{\n\t.reg .pred P1;\n\t"                               \
            "WL_%=:\n\t"                                                     \
            "mbarrier.try_wait.parity.acquire.cta.shared::cta.b64 P1, [%0], %1, 0x989680;\n\t" \
            "@P1 bra.uni WD_%=;\n\t"                                         \
            "bra.uni WL_%=;\n\t"                                             \
            "WD_%=:\n\t}"                                                    \
            :: "r"(_m), "r"(_p) : "memory");                                 \
    } } while (0)
#define TMA2D(dst, map, cx, cy, mbar) \
    asm volatile("cp.async.bulk.tensor.2d.shared::cta.global.tile.mbarrier::complete_tx::bytes " \
                 "[%0], [%1, {%2, %3}], [%4];"                               \
                 :: "r"(dst), "l"(map), "r"(cx), "r"(cy), "r"(mbar) : "memory")

#define MMA_F16(d0, d1, d2, d3, a0, a1, a2, a3, b0, b1) \
    asm volatile("mma.sync.aligned.m16n8k16.row.col.f32.f16.f16.f32 " \
                 "{%0,%1,%2,%3}, {%4,%5,%6,%7}, {%8,%9}, {%0,%1,%2,%3};" \
                 : "+f"(d0), "+f"(d1), "+f"(d2), "+f"(d3) \
                 : "r"(a0), "r"(a1), "r"(a2), "r"(a3), "r"(b0), "r"(b1))

#define LDSM_X4(r0, r1, r2, r3, addr) \
    asm volatile("ldmatrix.sync.aligned.m8n8.x4.shared.b16 {%0,%1,%2,%3}, [%4];" \
                 : "=r"(r0), "=r"(r1), "=r"(r2), "=r"(r3) : "r"(addr))

// ============================ conv kernel ============================
// Same structure as R13 (PASS @ 695us): CTA = 128 consecutive PADDED positions
// x 256 couts, TMA SW128 tiles, 3-stage mbarrier pipeline, 16 warps 4(M)x4(N),
// warp tile 32x64, fp16 m16n8k16, float32-value epilogue with border masking.
// CHANGE: fragment feeds via ldmatrix.x4 (6 issues/warp/ks instead of 24 LDS.32).
// ldmatrix delivers lane l <- (row l/4, cols (l%4)*2..+1) of each addressed
// 8-row matrix: identical to the R13-proven LDS coordinate map. Per-lane
// address = proven byte address with the SW128 XOR ((lane&7)<<4, since every
// tile row base is a multiple of 8).
static constexpr int A_BYTES   = 128 * 128;                 // 16384
static constexpr int B_BYTES   = 256 * 128;                 // 32768
static constexpr int STAGE_B   = A_BYTES + B_BYTES;         // 49152
static constexpr int NSTAGES   = 3;
static constexpr int TILES_B   = NSTAGES * STAGE_B;         // 147456
static constexpr int SMEM_DYN  = 1024 + TILES_B + 64;
static constexpr int NCHUNKS   = 36;
static constexpr int NCTA      = (TOTAL_POS + 127) / 128;   // 1625

__global__ void __launch_bounds__(512, 1)
conv_kernel(const __grid_constant__ CUtensorMap mapA,
            const __grid_constant__ CUtensorMap mapB,
            float* __restrict__ out) {
    extern __shared__ uint8_t smraw[];
    const uint32_t sb = ((uint32_t)__cvta_generic_to_shared(smraw) + 1023u) & ~1023u;
    const uint32_t bar0 = sb + TILES_B;

    const int tid  = threadIdx.x;
    const int lane = tid & 31;
    const int wid  = tid >> 5;
    const int warp_m = wid >> 2;       // 0..3 (32 M rows each)
    const int wn     = wid & 3;        // 0..3 (64 couts each)
    const int g   = lane >> 2;
    const int tig = lane & 3;
    const int p0  = blockIdx.x * 128;  // first padded position of this CTA

    if (tid == 0) {
        #pragma unroll
        for (int i = 0; i < NSTAGES; i++) MBAR_INIT(bar0 + i * 8, 1);
    }
    __syncthreads();

    // ---------------- TMA issue helper (single thread) ----------------
    auto issue = [&](int s) {
        const int slot = s % NSTAGES;
        const int tap = s >> 2, ch = s & 3;
        const int kh = tap / 3, kw = tap % 3;
        const uint32_t stg = sb + slot * STAGE_B;
        const uint32_t bar = bar0 + slot * 8;
        MBAR_EXPECT_TX(bar, (uint32_t)STAGE_B);
        TMA2D(stg,           &mapA, ch * 64, p0 + (kh - 1) * W_PAD + (kw - 1), bar);
        TMA2D(stg + A_BYTES, &mapB, ch * 64, tap * 256, bar);
    };

    if (tid == 0) { issue(0); issue(1); issue(2); }

    // ---------------- ldmatrix per-lane addressing ----------------
    // Shared XOR mask: all addressed rows have row&7 == lane&7.
    const uint32_t xm = (uint32_t)(lane & 7) << 4;
    // A: x4 matrices (row lane&15 within tile; col-half = lane>>4).
    const uint32_t a_colsel = (uint32_t)((lane >> 4) << 4);   // 0 or 16
    uint32_t a_base[2];
    #pragma unroll
    for (int mb = 0; mb < 2; mb++)
        a_base[mb] = (uint32_t)((warp_m * 32 + mb * 16 + (lane & 15)) * 128);
    // B: x4 per q covers nb=2q (rows 0-7) and nb=2q+1 (rows 8-15);
    // row-in-16 = (lane&7) + ((lane&16)?8:0), col-half = (lane&8)?16:0.
    const uint32_t b_colsel = (uint32_t)((lane & 8) << 1);    // 0 or 16
    uint32_t b_base[4];
    #pragma unroll
    for (int q = 0; q < 4; q++)
        b_base[q] = (uint32_t)(A_BYTES +
            (wn * 64 + q * 16 + (lane & 7) + ((lane & 16) >> 1)) * 128);

    float d[2][8][4];
    #pragma unroll
    for (int mb = 0; mb < 2; mb++)
        #pragma unroll
        for (int nb = 0; nb < 8; nb++)
            #pragma unroll
            for (int q = 0; q < 4; q++) d[mb][nb][q] = 0.0f;

    // ---------------- main loop ----------------
    #pragma unroll 1
    for (int c = 0; c < NCHUNKS; c++) {
        const int slot = c % NSTAGES;
        MBAR_WAIT(bar0 + slot * 8, (c / NSTAGES) & 1);
        const uint32_t stg = sb + slot * STAGE_B;

        #pragma unroll
        for (int ks = 0; ks < 4; ks++) {
            const uint32_t cA = ((uint32_t)(ks * 32) + a_colsel) ^ xm;
            const uint32_t cB = ((uint32_t)(ks * 32) + b_colsel) ^ xm;
            uint32_t a[2][4];
            #pragma unroll
            for (int mb = 0; mb < 2; mb++)
                LDSM_X4(a[mb][0], a[mb][1], a[mb][2], a[mb][3],
                        stg + a_base[mb] + cA);
            uint32_t b[8][2];
            #pragma unroll
            for (int q = 0; q < 4; q++)
                LDSM_X4(b[2 * q][0], b[2 * q][1], b[2 * q + 1][0], b[2 * q + 1][1],
                        stg + b_base[q] + cB);
            #pragma unroll
            for (int mb = 0; mb < 2; mb++)
                #pragma unroll
                for (int nb = 0; nb < 8; nb++)
                    MMA_F16(d[mb][nb][0], d[mb][nb][1], d[mb][nb][2], d[mb][nb][3],
                            a[mb][0], a[mb][1], a[mb][2], a[mb][3],
                            b[nb][0], b[nb][1]);
        }

        __syncthreads();                     // all warps done with this slot
        if (tid == 0 && c + NSTAGES < NCHUNKS) issue(c + NSTAGES);
    }

    // ---------------- epilogue: mask invalid padded positions, store f32 ----------------
    #pragma unroll
    for (int mb = 0; mb < 2; mb++) {
        #pragma unroll
        for (int r = 0; r < 2; r++) {        // row g and g+8
            const int pos = p0 + warp_m * 32 + mb * 16 + g + r * 8;
            if (pos >= TOTAL_POS) continue;
            const int n  = pos / (H_PAD * W_PAD);
            const int rm = pos % (H_PAD * W_PAD);
            const int hp = rm / W_PAD;
            const int wp = rm % W_PAD;
            if (hp < 1 || hp > H_IMG || wp < 1 || wp > W_IMG) continue;
            const int64_t obase =
                (((int64_t)n * H_IMG + (hp - 1)) * W_IMG + (wp - 1)) * C_OUT;
            #pragma unroll
            for (int nb = 0; nb < 8; nb++) {
                const int co = wn * 64 + nb * 8 + tig * 2;
                *reinterpret_cast<float2*>(out + obase + co) =
                    make_float2(d[mb][nb][2 * r], d[mb][nb][2 * r + 1]);
            }
        }
    }
}

// ============================ host launch ============================
typedef CUresult (*TmapEncodeFn)(
    CUtensorMap*, CUtensorMapDataType, cuuint32_t, void*,
    const cuuint64_t*, const cuuint64_t*, const cuuint32_t*, const cuuint32_t*,
    CUtensorMapInterleave, CUtensorMapSwizzle, CUtensorMapL2promotion,
    CUtensorMapFloatOOBfill);

extern "C" void kernel_launch(void* const* d_in, const int* in_sizes, int n_in,
                              void* d_out, int out_size) {
    (void)out_size;
    // Bind inputs BY SIZE: x has 51,380,224 elements, weight has 589,824.
    const int* x = (const int*)d_in[0];
    const int* w = (const int*)d_in[1];
    if (n_in >= 2 && in_sizes[0] < in_sizes[1]) {
        x = (const int*)d_in[1];
        w = (const int*)d_in[0];
    }
    float* out = (float*)d_out;

    const int64_t total_units = XUNITS + WUNITS;
    pack_kernel<<<(unsigned)((total_units + 255) / 256), 256>>>(x, w);

    // tensormaps
    void* xp = nullptr; void* wp = nullptr;
    cudaGetSymbolAddress(&xp, g_xh);
    cudaGetSymbolAddress(&wp, g_wh);

    TmapEncodeFn enc = nullptr;
    cudaDriverEntryPointQueryResult qres;
    cudaGetDriverEntryPointByVersion("cuTensorMapEncodeTiled", (void**)&enc,
                                     12000, cudaEnableDefault, &qres);

    CUtensorMap mapA, mapB;
    {
        cuuint64_t dims[2]    = {C_IN, (cuuint64_t)TOTAL_POS};
        cuuint64_t strides[1] = {C_IN * 2};                   // bytes
        cuuint32_t box[2]     = {64, 128};
        cuuint32_t es[2]      = {1, 1};
        enc(&mapA, CU_TENSOR_MAP_DATA_TYPE_FLOAT16, 2, xp, dims, strides, box, es,
            CU_TENSOR_MAP_INTERLEAVE_NONE, CU_TENSOR_MAP_SWIZZLE_128B,
            CU_TENSOR_MAP_L2_PROMOTION_L2_128B, CU_TENSOR_MAP_FLOAT_OOB_FILL_NONE);
    }
    {
        cuuint64_t dims[2]    = {C_IN, 9 * C_OUT};
        cuuint64_t strides[1] = {C_IN * 2};
        cuuint32_t box[2]     = {64, 256};
        cuuint32_t es[2]      = {1, 1};
        enc(&mapB, CU_TENSOR_MAP_DATA_TYPE_FLOAT16, 2, wp, dims, strides, box, es,
            CU_TENSOR_MAP_INTERLEAVE_NONE, CU_TENSOR_MAP_SWIZZLE_128B,
            CU_TENSOR_MAP_L2_PROMOTION_L2_128B, CU_TENSOR_MAP_FLOAT_OOB_FILL_NONE);
    }

    cudaFuncSetAttribute(conv_kernel, cudaFuncAttributeMaxDynamicSharedMemorySize, SMEM_DYN);
    conv_kernel<<<NCTA, 512, SMEM_DYN>>>(mapA, mapB, out);
}

// round 15
// speedup vs baseline: 3.2347x; 1.1117x over previous
#include <cuda_runtime.h>
#include <cuda_fp16.h>
#include <cuda.h>
#include <cstdint>

// ============================ problem dims ============================
#define N_IMG 16
#define H_IMG 112
#define W_IMG 112
#define C_IN  256
#define C_OUT 256
#define H_PAD 114
#define W_PAD 114
static constexpr int TOTAL_POS = N_IMG * H_PAD * W_PAD;   // 207936 padded positions

// padded activations as fp16: [pos][C_IN]  (~106 MB)
__device__ __align__(1024) __half g_xh[(size_t)TOTAL_POS * C_IN];
// weights as fp16, tap-major: [9][C_OUT][C_IN]
__device__ __align__(1024) __half g_wh[9 * C_OUT * C_IN];

// ============================ fused pack kernel (proven) ============================
static constexpr int64_t XUNITS = (int64_t)TOTAL_POS * 64;
static constexpr int     WUNITS = 9 * C_OUT * 64;

__global__ void pack_kernel(const int* __restrict__ x, const int* __restrict__ w) {
    int64_t i = (int64_t)blockIdx.x * blockDim.x + threadIdx.x;
    if (i < XUNITS) {
        int c4 = (int)(i & 63);
        int64_t p = i >> 6;
        int wp = (int)(p % W_PAD);
        int64_t t = p / W_PAD;
        int hp = (int)(t % H_PAD);
        int n  = (int)(t / H_PAD);
        uint2 wout = make_uint2(0u, 0u);
        if (hp >= 1 && hp <= H_IMG && wp >= 1 && wp <= W_IMG) {
            const int4 v = *reinterpret_cast<const int4*>(
                x + ((((int64_t)n * H_IMG + (hp - 1)) * W_IMG + (wp - 1)) * C_IN + c4 * 4));
            __half2 p0 = __floats2half2_rn((float)v.x, (float)v.y);
            __half2 p1 = __floats2half2_rn((float)v.z, (float)v.w);
            wout.x = *reinterpret_cast<uint32_t*>(&p0);
            wout.y = *reinterpret_cast<uint32_t*>(&p1);
        }
        reinterpret_cast<uint2*>(g_xh)[i] = wout;
    } else {
        int64_t j = i - XUNITS;
        if (j >= WUNITS) return;
        int c4 = (int)(j & 63);
        int t = (int)(j >> 6);
        int co = t % C_OUT;
        int tap = t / C_OUT;
        const int4 v = *reinterpret_cast<const int4*>(
            w + (((int64_t)co * 9 + tap) * C_IN + c4 * 4));
        __half2 p0 = __floats2half2_rn((float)v.x, (float)v.y);
        __half2 p1 = __floats2half2_rn((float)v.z, (float)v.w);
        reinterpret_cast<uint2*>(g_wh)[j] = make_uint2(
            *reinterpret_cast<uint32_t*>(&p0), *reinterpret_cast<uint32_t*>(&p1));
    }
}

// ============================ PTX helpers ============================
#define MBAR_INIT(addr, cnt) \
    asm volatile("mbarrier.init.shared.b64 [%0], %1;" :: "r"(addr), "r"(cnt) : "memory")
#define MBAR_EXPECT_TX(addr, bytes) \
    asm volatile("mbarrier.arrive.expect_tx.shared.b64 _, [%0], %1;" \
                 :: "r"(addr), "r"(bytes) : "memory")
#define MBAR_WAIT(addr, ph) do {                                             \
    uint32_t _m = (addr); uint32_t _p = (ph); uint32_t _d;                   \
    asm volatile("{\n\t.reg .pred p;\n\t"                                    \
        "mbarrier.try_wait.parity.acquire.cta.shared::cta.b64 p, [%1], %2;\n\t" \
        "selp.b32 %0, 1, 0, p;\n\t}"                                         \
        : "=r"(_d) : "r"(_m), "r"(_p) : "memory");                           \
    if (!_d) {                                                               \
        asm volatile("{\n\t.reg .pred P1;\n\t"                               \
            "WL_%=:\n\t"                                                     \
            "mbarrier.try_wait.parity.acquire.cta.shared::cta.b64 P1, [%0], %1, 0x989680;\n\t" \
            "@P1 bra.uni WD_%=;\n\t"                                         \
            "bra.uni WL_%=;\n\t"                                             \
            "WD_%=:\n\t}"                                                    \
            :: "r"(_m), "r"(_p) : "memory");                                 \
    } } while (0)
#define TMA2D(dst, map, cx, cy, mbar) \
    asm volatile("cp.async.bulk.tensor.2d.shared::cta.global.tile.mbarrier::complete_tx::bytes " \
                 "[%0], [%1, {%2, %3}], [%4];"                               \
                 :: "r"(dst), "l"(map), "r"(cx), "r"(cy), "r"(mbar) : "memory")

#define MMA_F16(d0, d1, d2, d3, a0, a1, a2, a3, b0, b1) \
    asm volatile("mma.sync.aligned.m16n8k16.row.col.f32.f16.f16.f32 " \
                 "{%0,%1,%2,%3}, {%4,%5,%6,%7}, {%8,%9}, {%0,%1,%2,%3};" \
                 : "+f"(d0), "+f"(d1), "+f"(d2), "+f"(d3) \
                 : "r"(a0), "r"(a1), "r"(a2), "r"(a3), "r"(b0), "r"(b1))

#define LDSM_X4(r0, r1, r2, r3, addr) \
    asm volatile("ldmatrix.sync.aligned.m8n8.x4.shared.b16 {%0,%1,%2,%3}, [%4];" \
                 : "=r"(r0), "=r"(r1), "=r"(r2), "=r"(r3) : "r"(addr))

// ============================ conv kernel ============================
// R14 structure (PASS @ 652us) with execution-shape change:
// CTA = 128 consecutive PADDED positions x 256 couts (identical TMA maps and
// 48KB stage layout), but 256 threads = 8 warps in 2(M)x4(N) grid, warp tile
// 64x64 (4x8 m16n8k16). Register budget/thread doubles (ptxas headroom to
// pipeline LDSM vs MMA); LDSM bytes/MMA drop 1.5x. 4 pipeline stages; TMA for
// chunk c+3 issued at the TOP of chunk c (slot (c+3)%4 freed by the
// __syncthreads at the end of chunk c-1).
static constexpr int A_BYTES   = 128 * 128;                 // 16384
static constexpr int B_BYTES   = 256 * 128;                 // 32768
static constexpr int STAGE_B   = A_BYTES + B_BYTES;         // 49152
static constexpr int NSTAGES   = 4;
static constexpr int TILES_B   = NSTAGES * STAGE_B;         // 196608
static constexpr int SMEM_DYN  = 1024 + TILES_B + 64;
static constexpr int NCHUNKS   = 36;
static constexpr int NCTA      = (TOTAL_POS + 127) / 128;   // 1625

__global__ void __launch_bounds__(256, 1)
conv_kernel(const __grid_constant__ CUtensorMap mapA,
            const __grid_constant__ CUtensorMap mapB,
            float* __restrict__ out) {
    extern __shared__ uint8_t smraw[];
    const uint32_t sb = ((uint32_t)__cvta_generic_to_shared(smraw) + 1023u) & ~1023u;
    const uint32_t bar0 = sb + TILES_B;

    const int tid  = threadIdx.x;
    const int lane = tid & 31;
    const int wid  = tid >> 5;
    const int warp_m = wid >> 2;       // 0..1 (64 M rows each)
    const int wn     = wid & 3;        // 0..3 (64 couts each)
    const int g   = lane >> 2;
    const int tig = lane & 3;
    const int p0  = blockIdx.x * 128;  // first padded position of this CTA

    if (tid == 0) {
        #pragma unroll
        for (int i = 0; i < NSTAGES; i++) MBAR_INIT(bar0 + i * 8, 1);
    }
    __syncthreads();

    // ---------------- TMA issue helper (single thread) ----------------
    auto issue = [&](int s) {
        const int slot = s % NSTAGES;
        const int tap = s >> 2, ch = s & 3;
        const int kh = tap / 3, kw = tap % 3;
        const uint32_t stg = sb + slot * STAGE_B;
        const uint32_t bar = bar0 + slot * 8;
        MBAR_EXPECT_TX(bar, (uint32_t)STAGE_B);
        TMA2D(stg,           &mapA, ch * 64, p0 + (kh - 1) * W_PAD + (kw - 1), bar);
        TMA2D(stg + A_BYTES, &mapB, ch * 64, tap * 256, bar);
    };

    if (tid == 0) { issue(0); issue(1); issue(2); }

    // ---------------- ldmatrix per-lane addressing ----------------
    const uint32_t xm = (uint32_t)(lane & 7) << 4;            // SW128 XOR mask
    const uint32_t a_colsel = (uint32_t)((lane >> 4) << 4);   // 0 or 16
    uint32_t a_base[4];
    #pragma unroll
    for (int mb = 0; mb < 4; mb++)
        a_base[mb] = (uint32_t)((warp_m * 64 + mb * 16 + (lane & 15)) * 128);
    const uint32_t b_colsel = (uint32_t)((lane & 8) << 1);    // 0 or 16
    uint32_t b_base[4];
    #pragma unroll
    for (int q = 0; q < 4; q++)
        b_base[q] = (uint32_t)(A_BYTES +
            (wn * 64 + q * 16 + (lane & 7) + ((lane & 16) >> 1)) * 128);

    float d[4][8][4];
    #pragma unroll
    for (int mb = 0; mb < 4; mb++)
        #pragma unroll
        for (int nb = 0; nb < 8; nb++)
            #pragma unroll
            for (int q = 0; q < 4; q++) d[mb][nb][q] = 0.0f;

    // ---------------- main loop ----------------
    #pragma unroll 1
    for (int c = 0; c < NCHUNKS; c++) {
        const int slot = c % NSTAGES;
        // prefetch chunk c+3 into slot (c+3)%4 (freed by sync at end of c-1)
        if (tid == 0 && c + NSTAGES - 1 < NCHUNKS) issue(c + NSTAGES - 1);
        MBAR_WAIT(bar0 + slot * 8, (c / NSTAGES) & 1);
        const uint32_t stg = sb + slot * STAGE_B;

        #pragma unroll
        for (int ks = 0; ks < 4; ks++) {
            const uint32_t cA = ((uint32_t)(ks * 32) + a_colsel) ^ xm;
            const uint32_t cB = ((uint32_t)(ks * 32) + b_colsel) ^ xm;
            uint32_t a[4][4];
            #pragma unroll
            for (int mb = 0; mb < 4; mb++)
                LDSM_X4(a[mb][0], a[mb][1], a[mb][2], a[mb][3],
                        stg + a_base[mb] + cA);
            uint32_t b[8][2];
            #pragma unroll
            for (int q = 0; q < 4; q++)
                LDSM_X4(b[2 * q][0], b[2 * q][1], b[2 * q + 1][0], b[2 * q + 1][1],
                        stg + b_base[q] + cB);
            #pragma unroll
            for (int mb = 0; mb < 4; mb++)
                #pragma unroll
                for (int nb = 0; nb < 8; nb++)
                    MMA_F16(d[mb][nb][0], d[mb][nb][1], d[mb][nb][2], d[mb][nb][3],
                            a[mb][0], a[mb][1], a[mb][2], a[mb][3],
                            b[nb][0], b[nb][1]);
        }

        __syncthreads();                     // all warps done with this slot
    }

    // ---------------- epilogue: mask invalid padded positions, store f32 ----------------
    #pragma unroll
    for (int mb = 0; mb < 4; mb++) {
        #pragma unroll
        for (int r = 0; r < 2; r++) {        // row g and g+8
            const int pos = p0 + warp_m * 64 + mb * 16 + g + r * 8;
            if (pos >= TOTAL_POS) continue;
            const int n  = pos / (H_PAD * W_PAD);
            const int rm = pos % (H_PAD * W_PAD);
            const int hp = rm / W_PAD;
            const int wp = rm % W_PAD;
            if (hp < 1 || hp > H_IMG || wp < 1 || wp > W_IMG) continue;
            const int64_t obase =
                (((int64_t)n * H_IMG + (hp - 1)) * W_IMG + (wp - 1)) * C_OUT;
            #pragma unroll
            for (int nb = 0; nb < 8; nb++) {
                const int co = wn * 64 + nb * 8 + tig * 2;
                *reinterpret_cast<float2*>(out + obase + co) =
                    make_float2(d[mb][nb][2 * r], d[mb][nb][2 * r + 1]);
            }
        }
    }
}

// ============================ host launch ============================
typedef CUresult (*TmapEncodeFn)(
    CUtensorMap*, CUtensorMapDataType, cuuint32_t, void*,
    const cuuint64_t*, const cuuint64_t*, const cuuint32_t*, const cuuint32_t*,
    CUtensorMapInterleave, CUtensorMapSwizzle, CUtensorMapL2promotion,
    CUtensorMapFloatOOBfill);

extern "C" void kernel_launch(void* const* d_in, const int* in_sizes, int n_in,
                              void* d_out, int out_size) {
    (void)out_size;
    // Bind inputs BY SIZE: x has 51,380,224 elements, weight has 589,824.
    const int* x = (const int*)d_in[0];
    const int* w = (const int*)d_in[1];
    if (n_in >= 2 && in_sizes[0] < in_sizes[1]) {
        x = (const int*)d_in[1];
        w = (const int*)d_in[0];
    }
    float* out = (float*)d_out;

    const int64_t total_units = XUNITS + WUNITS;
    pack_kernel<<<(unsigned)((total_units + 255) / 256), 256>>>(x, w);

    // tensormaps
    void* xp = nullptr; void* wp = nullptr;
    cudaGetSymbolAddress(&xp, g_xh);
    cudaGetSymbolAddress(&wp, g_wh);

    TmapEncodeFn enc = nullptr;
    cudaDriverEntryPointQueryResult qres;
    cudaGetDriverEntryPointByVersion("cuTensorMapEncodeTiled", (void**)&enc,
                                     12000, cudaEnableDefault, &qres);

    CUtensorMap mapA, mapB;
    {
        cuuint64_t dims[2]    = {C_IN, (cuuint64_t)TOTAL_POS};
        cuuint64_t strides[1] = {C_IN * 2};                   // bytes
        cuuint32_t box[2]     = {64, 128};
        cuuint32_t es[2]      = {1, 1};
        enc(&mapA, CU_TENSOR_MAP_DATA_TYPE_FLOAT16, 2, xp, dims, strides, box, es,
            CU_TENSOR_MAP_INTERLEAVE_NONE, CU_TENSOR_MAP_SWIZZLE_128B,
            CU_TENSOR_MAP_L2_PROMOTION_L2_128B, CU_TENSOR_MAP_FLOAT_OOB_FILL_NONE);
    }
    {
        cuuint64_t dims[2]    = {C_IN, 9 * C_OUT};
        cuuint64_t strides[1] = {C_IN * 2};
        cuuint32_t box[2]     = {64, 256};
        cuuint32_t es[2]      = {1, 1};
        enc(&mapB, CU_TENSOR_MAP_DATA_TYPE_FLOAT16, 2, wp, dims, strides, box, es,
            CU_TENSOR_MAP_INTERLEAVE_NONE, CU_TENSOR_MAP_SWIZZLE_128B,
            CU_TENSOR_MAP_L2_PROMOTION_L2_128B, CU_TENSOR_MAP_FLOAT_OOB_FILL_NONE);
    }

    cudaFuncSetAttribute(conv_kernel, cudaFuncAttributeMaxDynamicSharedMemorySize, SMEM_DYN);
    conv_kernel<<<NCTA, 256, SMEM_DYN>>>(mapA, mapB, out);
}